// round 14
// baseline (speedup 1.0000x reference)
#include <cuda_runtime.h>
#include <cuda_fp16.h>
#include <cstdint>

#define MDIM 4096
#define NDIM 4096
#define KDIM 4096

#define BM 128
#define BN 128
#define BK 64
#define STAGES 3
#define KT_ITERS (KDIM / BK)      // 64
#define NTILES ((MDIM / BM) * (NDIM / BN))   // 1024
#define GRID_PERSIST 296                      // 148 SMs x 2 CTAs

#define A_TILE_B 16384            // 128 rows x 128B (swizzled)
#define B_TILE_B 16384            // 2 halves x 64 rows x 128B (swizzled)
#define STAGE_B  (A_TILE_B + B_TILE_B)       // 32768
#define SM_TOTAL (STAGES * STAGE_B)          // 98304

// Scratch (allocation-free rule: __device__ globals)
__device__ __half g_x16[(size_t)MDIM * KDIM];   // A [M][K]
__device__ __half g_w16[(size_t)KDIM * NDIM];   // W [K][N]
__device__ unsigned int g_tile_ctr;             // dynamic tile queue

__device__ __forceinline__ uint32_t smem_u32(const void* p) {
    return (uint32_t)__cvta_generic_to_shared(p);
}

// ---------------------------------------------------------------------------
// Kernel 1: merged prep. Blocks [0, 8192): dequant W. [8192, 24576): cvt x.
// Block 0 also resets the GEMM tile counter (stream-ordered before k_gemm,
// so every graph replay starts from 0 — deterministic).
// ---------------------------------------------------------------------------
__global__ void k_prep(const float* __restrict__ x,
                       const int* __restrict__ packed,
                       const float* __restrict__ scales,
                       const float* __restrict__ zeros) {
    int b = blockIdx.x;
    if (b == 0 && threadIdx.x == 0) g_tile_ctr = 0;
    if (b < 8192) {
        // dequant: packed[i, n] holds k = i*8 + j in nibble j; group g = i/16
        int idx = b * 256 + threadIdx.x;       // over (K/8)*N = 2M
        int n = idx & (NDIM - 1);
        int i = idx >> 12;
        int g = i >> 4;
        float s = __ldg(&scales[g * NDIM + n]);
        float z = __ldg(&zeros[g * NDIM + n]);
        int p = __ldg(&packed[idx]);
#pragma unroll
        for (int j = 0; j < 8; j++) {
            int w = (p >> (4 * j)) & 15;
            g_w16[(size_t)(i * 8 + j) * NDIM + n] = __float2half(((float)w - z) * s);
        }
    } else {
        // x fp32 -> fp16, 4 elems/thread
        int idx = (b - 8192) * 256 + threadIdx.x;   // over 16M/4
        float4 v = ((const float4*)x)[idx];
        ((__half2*)g_x16)[idx * 2 + 0] = __floats2half2_rn(v.x, v.y);
        ((__half2*)g_x16)[idx * 2 + 1] = __floats2half2_rn(v.z, v.w);
    }
}

// ---------------------------------------------------------------------------
// Kernel 2: fp16 GEMM (mma.sync f32-acc), + bias. PERSISTENT grid of 296
// CTAs pulling 128x128 tiles from a global atomic queue (kills the 3.46-wave
// tail quantization: 86.5% -> ~97% slot efficiency).
// Per tile: 256 threads (8 warps 4x2, warp tile 32x64), BK=64, 3-stage
// cp.async pipeline, XOR-swizzled smem (128B rows), 2 CTAs/SM.
// A smem: row r (0..127), 16B-chunk c (0..7): off = r*128 + ((c^(r&7))<<4)
// B smem: half h = n>=64, row k (0..63), chunk c (0..7):
//         off = h*8192 + k*128 + ((c^(k&7))<<4)
// ---------------------------------------------------------------------------
#define LOAD_STAGE(KT_, SLOT_) do {                                           \
    int k0_ = (KT_) * BK;                                                     \
    uint32_t sA_ = sbase + (SLOT_) * STAGE_B;                                 \
    uint32_t sB_ = sA_ + A_TILE_B;                                            \
    _Pragma("unroll")                                                         \
    for (int j_ = 0; j_ < 4; j_++) {                                          \
        int c_ = tid + j_ * 256;                                              \
        int ar_ = c_ >> 3, ac_ = c_ & 7;                                      \
        const __half* gA_ = g_x16 + (size_t)(bm + ar_) * KDIM + k0_ + ac_ * 8;\
        uint32_t soA_ = sA_ + ar_ * 128 + (((ac_ ^ (ar_ & 7))) << 4);         \
        asm volatile("cp.async.cg.shared.global [%0], [%1], 16;"              \
                     :: "r"(soA_), "l"(gA_) : "memory");                      \
    }                                                                         \
    _Pragma("unroll")                                                         \
    for (int j_ = 0; j_ < 4; j_++) {                                          \
        int c_ = tid + j_ * 256;                                              \
        int br_ = c_ >> 4, bc_ = c_ & 15;                                     \
        int h_ = bc_ >> 3, cc_ = bc_ & 7;                                     \
        const __half* gB_ = g_w16 + (size_t)(k0_ + br_) * NDIM + bn + bc_ * 8;\
        uint32_t soB_ = sB_ + h_ * 8192 + br_ * 128 + ((cc_ ^ (br_ & 7)) << 4);\
        asm volatile("cp.async.cg.shared.global [%0], [%1], 16;"              \
                     :: "r"(soB_), "l"(gB_) : "memory");                      \
    }                                                                         \
    asm volatile("cp.async.commit_group;" ::: "memory");                      \
} while (0)

__global__ void __launch_bounds__(256, 2)
k_gemm(const float* __restrict__ bias, float* __restrict__ C) {
    extern __shared__ char smem[];
    const uint32_t sbase = smem_u32(smem);
    __shared__ unsigned int s_tile;

    const int tid  = threadIdx.x;
    const int warp = tid >> 5;
    const int lane = tid & 31;
    const int wm = warp & 3;     // 4 warps along M (32 rows each)
    const int wn = warp >> 2;    // 2 warps along N (64 cols each)

    while (true) {
        if (tid == 0) s_tile = atomicAdd(&g_tile_ctr, 1u);
        __syncthreads();                 // broadcast + guard smem reuse
        unsigned int t = s_tile;
        if (t >= NTILES) break;
        const int bm = (int)(t >> 5) * BM;     // 32 tiles along N
        const int bn = (int)(t & 31) * BN;

        float acc[2][8][4];
#pragma unroll
        for (int mt = 0; mt < 2; mt++)
#pragma unroll
            for (int nt = 0; nt < 8; nt++)
#pragma unroll
                for (int r = 0; r < 4; r++) acc[mt][nt][r] = 0.0f;

        LOAD_STAGE(0, 0);
        LOAD_STAGE(1, 1);

        int slot = 0;
        int nslot = 2;
        for (int kt = 0; kt < KT_ITERS; kt++) {
            if (kt < KT_ITERS - 1)
                asm volatile("cp.async.wait_group 1;" ::: "memory");
            else
                asm volatile("cp.async.wait_group 0;" ::: "memory");
            __syncthreads();

            if (kt + 2 < KT_ITERS) LOAD_STAGE(kt + 2, nslot);

            uint32_t sA = sbase + slot * STAGE_B;
            uint32_t sB = sA + A_TILE_B + wn * 8192;

#pragma unroll
            for (int ks = 0; ks < 4; ks++) {          // 4 x k16 per BK=64
                uint32_t a[2][4];
#pragma unroll
                for (int mt = 0; mt < 2; mt++) {
                    int row = wm * 32 + mt * 16 + (lane & 15);
                    int c16 = ks * 2 + (lane >> 4);
                    uint32_t addr = sA + row * 128 + ((c16 ^ (row & 7)) << 4);
                    asm volatile(
                        "ldmatrix.sync.aligned.m8n8.x4.shared.b16 {%0,%1,%2,%3}, [%4];"
                        : "=r"(a[mt][0]), "=r"(a[mt][1]), "=r"(a[mt][2]), "=r"(a[mt][3])
                        : "r"(addr));
                }
                uint32_t b[8][2];
#pragma unroll
                for (int nq = 0; nq < 4; nq++) {
                    int row = ks * 16 + (lane & 15);
                    int c16 = nq * 2 + (lane >> 4);
                    uint32_t addr = sB + row * 128 + ((c16 ^ (row & 7)) << 4);
                    asm volatile(
                        "ldmatrix.sync.aligned.m8n8.x4.trans.shared.b16 {%0,%1,%2,%3}, [%4];"
                        : "=r"(b[nq * 2][0]), "=r"(b[nq * 2][1]),
                          "=r"(b[nq * 2 + 1][0]), "=r"(b[nq * 2 + 1][1])
                        : "r"(addr));
                }
#pragma unroll
                for (int mt = 0; mt < 2; mt++) {
#pragma unroll
                    for (int nt = 0; nt < 8; nt++) {
                        asm volatile(
                            "mma.sync.aligned.m16n8k16.row.col.f32.f16.f16.f32 "
                            "{%0,%1,%2,%3}, {%4,%5,%6,%7}, {%8,%9}, {%0,%1,%2,%3};"
                            : "+f"(acc[mt][nt][0]), "+f"(acc[mt][nt][1]),
                              "+f"(acc[mt][nt][2]), "+f"(acc[mt][nt][3])
                            : "r"(a[mt][0]), "r"(a[mt][1]), "r"(a[mt][2]), "r"(a[mt][3]),
                              "r"(b[nt][0]), "r"(b[nt][1]));
                    }
                }
            }

            slot = (slot == STAGES - 1) ? 0 : slot + 1;
            nslot = (nslot == STAGES - 1) ? 0 : nslot + 1;
        }

        // epilogue with bias
#pragma unroll
        for (int mt = 0; mt < 2; mt++) {
            int row0 = bm + wm * 32 + mt * 16 + (lane >> 2);
#pragma unroll
            for (int nt = 0; nt < 8; nt++) {
                int col = bn + wn * 64 + nt * 8 + (lane & 3) * 2;
                float b0 = __ldg(&bias[col]);
                float b1 = __ldg(&bias[col + 1]);
                float2 v0 = make_float2(acc[mt][nt][0] + b0, acc[mt][nt][1] + b1);
                float2 v1 = make_float2(acc[mt][nt][2] + b0, acc[mt][nt][3] + b1);
                *(float2*)&C[(size_t)row0 * NDIM + col] = v0;
                *(float2*)&C[(size_t)(row0 + 8) * NDIM + col] = v1;
            }
        }
    }
}

// ---------------------------------------------------------------------------
// Launch: inputs: x, W_q_packed, scales, zeros, bias
// ---------------------------------------------------------------------------
extern "C" void kernel_launch(void* const* d_in, const int* in_sizes, int n_in,
                              void* d_out, int out_size) {
    const float* x      = (const float*)d_in[0];
    const int*   wq     = (const int*)d_in[1];
    const float* scales = (const float*)d_in[2];
    const float* zeros  = (const float*)d_in[3];
    const float* bias   = (const float*)d_in[4];
    float* out = (float*)d_out;

    {   // merged prep: 8192 dequant blocks + 16384 cvt blocks (+ ctr reset)
        k_prep<<<24576, 256>>>(x, wq, scales, zeros);
    }
    {
        cudaFuncSetAttribute(k_gemm, cudaFuncAttributeMaxDynamicSharedMemorySize, SM_TOTAL);
        k_gemm<<<GRID_PERSIST, 256, SM_TOTAL>>>(bias, out);
    }
}

// round 15
// speedup vs baseline: 1.2889x; 1.2889x over previous
#include <cuda_runtime.h>
#include <cuda_fp16.h>
#include <cstdint>

#define MDIM 4096
#define NDIM 4096
#define KDIM 4096

#define BM 128
#define BN 128
#define BK 64
#define STAGES 3
#define KT_ITERS (KDIM / BK)      // 64
#define NTILES ((MDIM / BM) * (NDIM / BN))   // 1024
#define GRID_PERSIST 296                      // 148 SMs x 2 CTAs

#define A_TILE_B 16384            // 128 rows x 128B (swizzled)
#define B_TILE_B 16384            // 2 halves x 64 rows x 128B (swizzled)
#define STAGE_B  (A_TILE_B + B_TILE_B)       // 32768
#define SM_TOTAL (STAGES * STAGE_B)          // 98304

// Scratch (allocation-free rule: __device__ globals)
__device__ __half g_x16[(size_t)MDIM * KDIM];   // A [M][K]
__device__ __half g_w16[(size_t)KDIM * NDIM];   // W [K][N]

__device__ __forceinline__ uint32_t smem_u32(const void* p) {
    return (uint32_t)__cvta_generic_to_shared(p);
}

// ---------------------------------------------------------------------------
// Kernel 1: merged prep. Blocks [0, 8192): dequant W. [8192, 24576): cvt x.
// ---------------------------------------------------------------------------
__global__ void k_prep(const float* __restrict__ x,
                       const int* __restrict__ packed,
                       const float* __restrict__ scales,
                       const float* __restrict__ zeros) {
    int b = blockIdx.x;
    if (b < 8192) {
        // dequant: packed[i, n] holds k = i*8 + j in nibble j; group g = i/16
        int idx = b * 256 + threadIdx.x;       // over (K/8)*N = 2M
        int n = idx & (NDIM - 1);
        int i = idx >> 12;
        int g = i >> 4;
        float s = __ldg(&scales[g * NDIM + n]);
        float z = __ldg(&zeros[g * NDIM + n]);
        int p = __ldg(&packed[idx]);
#pragma unroll
        for (int j = 0; j < 8; j++) {
            int w = (p >> (4 * j)) & 15;
            g_w16[(size_t)(i * 8 + j) * NDIM + n] = __float2half(((float)w - z) * s);
        }
    } else {
        // x fp32 -> fp16, 4 elems/thread
        int idx = (b - 8192) * 256 + threadIdx.x;   // over 16M/4
        float4 v = ((const float4*)x)[idx];
        ((__half2*)g_x16)[idx * 2 + 0] = __floats2half2_rn(v.x, v.y);
        ((__half2*)g_x16)[idx * 2 + 1] = __floats2half2_rn(v.z, v.w);
    }
}

// ---------------------------------------------------------------------------
// Kernel 2: fp16 GEMM (mma.sync f32-acc), + bias. STATIC persistent grid of
// 296 CTAs; CTA bid processes tiles bid, bid+296, ... (uniform-register
// friendly, no atomics, no shared broadcast). The 3-stage cp.async pipeline
// runs CONTINUOUSLY across tile boundaries (loads for the next tile overlap
// the last k-iterations of the current tile); the epilogue (regs -> C) sits
// between k-loops with no extra synchronization.
// Per tile: 256 threads (8 warps 4x2, warp tile 32x64), BK=64,
// XOR-swizzled smem (128B rows), 2 CTAs/SM.
// ---------------------------------------------------------------------------
#define LOAD_AT(T_, KT_, SLOT_) do {                                          \
    int lbm_ = ((T_) >> 5) * BM;                                              \
    int lbn_ = ((T_) & 31) * BN;                                              \
    int k0_ = (KT_) * BK;                                                     \
    uint32_t sA_ = sbase + (SLOT_) * STAGE_B;                                 \
    uint32_t sB_ = sA_ + A_TILE_B;                                            \
    _Pragma("unroll")                                                         \
    for (int j_ = 0; j_ < 4; j_++) {                                          \
        int c_ = tid + j_ * 256;                                              \
        int ar_ = c_ >> 3, ac_ = c_ & 7;                                      \
        const __half* gA_ = g_x16 + (size_t)(lbm_ + ar_) * KDIM + k0_ + ac_ * 8;\
        uint32_t soA_ = sA_ + ar_ * 128 + (((ac_ ^ (ar_ & 7))) << 4);         \
        asm volatile("cp.async.cg.shared.global [%0], [%1], 16;"              \
                     :: "r"(soA_), "l"(gA_) : "memory");                      \
    }                                                                         \
    _Pragma("unroll")                                                         \
    for (int j_ = 0; j_ < 4; j_++) {                                          \
        int c_ = tid + j_ * 256;                                              \
        int br_ = c_ >> 4, bc_ = c_ & 15;                                     \
        int h_ = bc_ >> 3, cc_ = bc_ & 7;                                     \
        const __half* gB_ = g_w16 + (size_t)(k0_ + br_) * NDIM + lbn_ + bc_ * 8;\
        uint32_t soB_ = sB_ + h_ * 8192 + br_ * 128 + ((cc_ ^ (br_ & 7)) << 4);\
        asm volatile("cp.async.cg.shared.global [%0], [%1], 16;"              \
                     :: "r"(soB_), "l"(gB_) : "memory");                      \
    }                                                                         \
    asm volatile("cp.async.commit_group;" ::: "memory");                      \
} while (0)

__global__ void __launch_bounds__(256, 2)
k_gemm(const float* __restrict__ bias, float* __restrict__ C) {
    extern __shared__ char smem[];
    const uint32_t sbase = smem_u32(smem);

    const int tid  = threadIdx.x;
    const int warp = tid >> 5;
    const int lane = tid & 31;
    const int wm = warp & 3;     // 4 warps along M (32 rows each)
    const int wn = warp >> 2;    // 2 warps along N (64 cols each)
    const int bid = blockIdx.x;

    const int nt_mine = (bid < (NTILES - 3 * GRID_PERSIST)) ? 4 : 3;  // 136 CTAs get 4
    const int TOTL = nt_mine * KT_ITERS;

    int t = bid;
    LOAD_AT(t, 0, 0);
    LOAD_AT(t, 1, 1);

    int slot = 0;
    int nslot = 2;
    int L = 0;                    // linear (tile, kt) index — continuous pipeline

    for (int i = 0; i < nt_mine; i++) {
        float acc[2][8][4];
#pragma unroll
        for (int mt = 0; mt < 2; mt++)
#pragma unroll
            for (int nt = 0; nt < 8; nt++)
#pragma unroll
                for (int r = 0; r < 4; r++) acc[mt][nt][r] = 0.0f;

        for (int kt = 0; kt < KT_ITERS; kt++, L++) {
            if (L < TOTL - 1)
                asm volatile("cp.async.wait_group 1;" ::: "memory");
            else
                asm volatile("cp.async.wait_group 0;" ::: "memory");
            __syncthreads();

            if (L + 2 < TOTL) {
                int lkt = kt + 2;
                int lt = t;
                if (lkt >= KT_ITERS) { lkt -= KT_ITERS; lt += GRID_PERSIST; }
                LOAD_AT(lt, lkt, nslot);
            }

            uint32_t sA = sbase + slot * STAGE_B;
            uint32_t sB = sA + A_TILE_B + wn * 8192;

#pragma unroll
            for (int ks = 0; ks < 4; ks++) {          // 4 x k16 per BK=64
                uint32_t a[2][4];
#pragma unroll
                for (int mt = 0; mt < 2; mt++) {
                    int row = wm * 32 + mt * 16 + (lane & 15);
                    int c16 = ks * 2 + (lane >> 4);
                    uint32_t addr = sA + row * 128 + ((c16 ^ (row & 7)) << 4);
                    asm volatile(
                        "ldmatrix.sync.aligned.m8n8.x4.shared.b16 {%0,%1,%2,%3}, [%4];"
                        : "=r"(a[mt][0]), "=r"(a[mt][1]), "=r"(a[mt][2]), "=r"(a[mt][3])
                        : "r"(addr));
                }
                uint32_t b[8][2];
#pragma unroll
                for (int nq = 0; nq < 4; nq++) {
                    int row = ks * 16 + (lane & 15);
                    int c16 = nq * 2 + (lane >> 4);
                    uint32_t addr = sB + row * 128 + ((c16 ^ (row & 7)) << 4);
                    asm volatile(
                        "ldmatrix.sync.aligned.m8n8.x4.trans.shared.b16 {%0,%1,%2,%3}, [%4];"
                        : "=r"(b[nq * 2][0]), "=r"(b[nq * 2][1]),
                          "=r"(b[nq * 2 + 1][0]), "=r"(b[nq * 2 + 1][1])
                        : "r"(addr));
                }
#pragma unroll
                for (int mt = 0; mt < 2; mt++) {
#pragma unroll
                    for (int nt = 0; nt < 8; nt++) {
                        asm volatile(
                            "mma.sync.aligned.m16n8k16.row.col.f32.f16.f16.f32 "
                            "{%0,%1,%2,%3}, {%4,%5,%6,%7}, {%8,%9}, {%0,%1,%2,%3};"
                            : "+f"(acc[mt][nt][0]), "+f"(acc[mt][nt][1]),
                              "+f"(acc[mt][nt][2]), "+f"(acc[mt][nt][3])
                            : "r"(a[mt][0]), "r"(a[mt][1]), "r"(a[mt][2]), "r"(a[mt][3]),
                              "r"(b[nt][0]), "r"(b[nt][1]));
                    }
                }
            }

            slot = (slot == STAGES - 1) ? 0 : slot + 1;
            nslot = (nslot == STAGES - 1) ? 0 : nslot + 1;
        }

        // epilogue with bias (regs -> C only; next tile's loads already in flight)
        {
            const int bm = (t >> 5) * BM;
            const int bn = (t & 31) * BN;
#pragma unroll
            for (int mt = 0; mt < 2; mt++) {
                int row0 = bm + wm * 32 + mt * 16 + (lane >> 2);
#pragma unroll
                for (int nt = 0; nt < 8; nt++) {
                    int col = bn + wn * 64 + nt * 8 + (lane & 3) * 2;
                    float b0 = __ldg(&bias[col]);
                    float b1 = __ldg(&bias[col + 1]);
                    float2 v0 = make_float2(acc[mt][nt][0] + b0, acc[mt][nt][1] + b1);
                    float2 v1 = make_float2(acc[mt][nt][2] + b0, acc[mt][nt][3] + b1);
                    *(float2*)&C[(size_t)row0 * NDIM + col] = v0;
                    *(float2*)&C[(size_t)(row0 + 8) * NDIM + col] = v1;
                }
            }
        }
        t += GRID_PERSIST;
    }
}

// ---------------------------------------------------------------------------
// Launch: inputs: x, W_q_packed, scales, zeros, bias
// ---------------------------------------------------------------------------
extern "C" void kernel_launch(void* const* d_in, const int* in_sizes, int n_in,
                              void* d_out, int out_size) {
    const float* x      = (const float*)d_in[0];
    const int*   wq     = (const int*)d_in[1];
    const float* scales = (const float*)d_in[2];
    const float* zeros  = (const float*)d_in[3];
    const float* bias   = (const float*)d_in[4];
    float* out = (float*)d_out;

    {   // merged prep: 8192 dequant blocks + 16384 cvt blocks
        k_prep<<<24576, 256>>>(x, wq, scales, zeros);
    }
    {
        cudaFuncSetAttribute(k_gemm, cudaFuncAttributeMaxDynamicSharedMemorySize, SM_TOTAL);
        k_gemm<<<GRID_PERSIST, 256, SM_TOTAL>>>(bias, out);
    }
}

// round 16
// speedup vs baseline: 1.2912x; 1.0018x over previous
#include <cuda_runtime.h>
#include <cuda_fp16.h>
#include <cstdint>

#define MDIM 4096
#define NDIM 4096
#define KDIM 4096

#define BM 128
#define BN 128
#define BK 64
#define STAGES 3
#define KT_ITERS (KDIM / BK)      // 64
#define NTILES ((MDIM / BM) * (NDIM / BN))   // 1024
#define GRID_PERSIST 296                      // 148 SMs x 2 CTAs

#define A_TILE_B 16384            // 128 rows x 128B (swizzled)
#define B_TILE_B 16384            // 2 halves x 64 rows x 128B (swizzled)
#define STAGE_B  (A_TILE_B + B_TILE_B)       // 32768
#define SM_TOTAL (STAGES * STAGE_B)          // 98304

// Scratch (allocation-free rule: __device__ globals)
__device__ __half g_x16[(size_t)MDIM * KDIM];   // A [M][K]
__device__ __half g_w16[(size_t)KDIM * NDIM];   // W [K][N]

__device__ __forceinline__ uint32_t smem_u32(const void* p) {
    return (uint32_t)__cvta_generic_to_shared(p);
}

// ---------------------------------------------------------------------------
// Kernel 1: merged prep. Blocks [0, 8192): dequant W. [8192, 24576): cvt x.
// ---------------------------------------------------------------------------
__global__ void k_prep(const float* __restrict__ x,
                       const int* __restrict__ packed,
                       const float* __restrict__ scales,
                       const float* __restrict__ zeros) {
    int b = blockIdx.x;
    if (b < 8192) {
        // dequant: packed[i, n] holds k = i*8 + j in nibble j; group g = i/16
        int idx = b * 256 + threadIdx.x;       // over (K/8)*N = 2M
        int n = idx & (NDIM - 1);
        int i = idx >> 12;
        int g = i >> 4;
        float s = __ldg(&scales[g * NDIM + n]);
        float z = __ldg(&zeros[g * NDIM + n]);
        int p = __ldg(&packed[idx]);
#pragma unroll
        for (int j = 0; j < 8; j++) {
            int w = (p >> (4 * j)) & 15;
            g_w16[(size_t)(i * 8 + j) * NDIM + n] = __float2half(((float)w - z) * s);
        }
    } else {
        // x fp32 -> fp16, 4 elems/thread
        int idx = (b - 8192) * 256 + threadIdx.x;   // over 16M/4
        float4 v = ((const float4*)x)[idx];
        ((__half2*)g_x16)[idx * 2 + 0] = __floats2half2_rn(v.x, v.y);
        ((__half2*)g_x16)[idx * 2 + 1] = __floats2half2_rn(v.z, v.w);
    }
}

// ---------------------------------------------------------------------------
// Kernel 2: fp16 GEMM (mma.sync f32-acc), + bias. STATIC persistent grid of
// 296 CTAs (tiles bid, bid+296, ...), continuous 3-stage cp.async pipeline
// across tile boundaries. 256 threads (8 warps 4x2, warp tile 32x64),
// XOR-swizzled smem (128B rows), 2 CTAs/SM.
// NOTE: ldmatrix is non-volatile + "memory" clobber (ordered vs barriers,
// free vs mma); mma is non-volatile pure-register asm — lets ptxas interleave
// HMMA with subsequent LDSM to cover shared-memory latency.
// ---------------------------------------------------------------------------
#define LOAD_AT(T_, KT_, SLOT_) do {                                          \
    int lbm_ = ((T_) >> 5) * BM;                                              \
    int lbn_ = ((T_) & 31) * BN;                                              \
    int k0_ = (KT_) * BK;                                                     \
    uint32_t sA_ = sbase + (SLOT_) * STAGE_B;                                 \
    uint32_t sB_ = sA_ + A_TILE_B;                                            \
    _Pragma("unroll")                                                         \
    for (int j_ = 0; j_ < 4; j_++) {                                          \
        int c_ = tid + j_ * 256;                                              \
        int ar_ = c_ >> 3, ac_ = c_ & 7;                                      \
        const __half* gA_ = g_x16 + (size_t)(lbm_ + ar_) * KDIM + k0_ + ac_ * 8;\
        uint32_t soA_ = sA_ + ar_ * 128 + (((ac_ ^ (ar_ & 7))) << 4);         \
        asm volatile("cp.async.cg.shared.global [%0], [%1], 16;"              \
                     :: "r"(soA_), "l"(gA_) : "memory");                      \
    }                                                                         \
    _Pragma("unroll")                                                         \
    for (int j_ = 0; j_ < 4; j_++) {                                          \
        int c_ = tid + j_ * 256;                                              \
        int br_ = c_ >> 4, bc_ = c_ & 15;                                     \
        int h_ = bc_ >> 3, cc_ = bc_ & 7;                                     \
        const __half* gB_ = g_w16 + (size_t)(k0_ + br_) * NDIM + lbn_ + bc_ * 8;\
        uint32_t soB_ = sB_ + h_ * 8192 + br_ * 128 + ((cc_ ^ (br_ & 7)) << 4);\
        asm volatile("cp.async.cg.shared.global [%0], [%1], 16;"              \
                     :: "r"(soB_), "l"(gB_) : "memory");                      \
    }                                                                         \
    asm volatile("cp.async.commit_group;" ::: "memory");                      \
} while (0)

__global__ void __launch_bounds__(256, 2)
k_gemm(const float* __restrict__ bias, float* __restrict__ C) {
    extern __shared__ char smem[];
    const uint32_t sbase = smem_u32(smem);

    const int tid  = threadIdx.x;
    const int warp = tid >> 5;
    const int lane = tid & 31;
    const int wm = warp & 3;     // 4 warps along M (32 rows each)
    const int wn = warp >> 2;    // 2 warps along N (64 cols each)
    const int bid = blockIdx.x;

    const int nt_mine = (bid < (NTILES - 3 * GRID_PERSIST)) ? 4 : 3;  // 136 CTAs get 4
    const int TOTL = nt_mine * KT_ITERS;

    int t = bid;
    LOAD_AT(t, 0, 0);
    LOAD_AT(t, 1, 1);

    int slot = 0;
    int nslot = 2;
    int L = 0;                    // linear (tile, kt) index — continuous pipeline

    for (int i = 0; i < nt_mine; i++) {
        float acc[2][8][4];
#pragma unroll
        for (int mt = 0; mt < 2; mt++)
#pragma unroll
            for (int nt = 0; nt < 8; nt++)
#pragma unroll
                for (int r = 0; r < 4; r++) acc[mt][nt][r] = 0.0f;

        for (int kt = 0; kt < KT_ITERS; kt++, L++) {
            if (L < TOTL - 1)
                asm volatile("cp.async.wait_group 1;" ::: "memory");
            else
                asm volatile("cp.async.wait_group 0;" ::: "memory");
            __syncthreads();

            if (L + 2 < TOTL) {
                int lkt = kt + 2;
                int lt = t;
                if (lkt >= KT_ITERS) { lkt -= KT_ITERS; lt += GRID_PERSIST; }
                LOAD_AT(lt, lkt, nslot);
            }

            uint32_t sA = sbase + slot * STAGE_B;
            uint32_t sB = sA + A_TILE_B + wn * 8192;

#pragma unroll
            for (int ks = 0; ks < 4; ks++) {          // 4 x k16 per BK=64
                uint32_t a[2][4];
#pragma unroll
                for (int mt = 0; mt < 2; mt++) {
                    int row = wm * 32 + mt * 16 + (lane & 15);
                    int c16 = ks * 2 + (lane >> 4);
                    uint32_t addr = sA + row * 128 + ((c16 ^ (row & 7)) << 4);
                    asm("ldmatrix.sync.aligned.m8n8.x4.shared.b16 {%0,%1,%2,%3}, [%4];"
                        : "=r"(a[mt][0]), "=r"(a[mt][1]), "=r"(a[mt][2]), "=r"(a[mt][3])
                        : "r"(addr) : "memory");
                }
                uint32_t b[8][2];
#pragma unroll
                for (int nq = 0; nq < 4; nq++) {
                    int row = ks * 16 + (lane & 15);
                    int c16 = nq * 2 + (lane >> 4);
                    uint32_t addr = sB + row * 128 + ((c16 ^ (row & 7)) << 4);
                    asm("ldmatrix.sync.aligned.m8n8.x4.trans.shared.b16 {%0,%1,%2,%3}, [%4];"
                        : "=r"(b[nq * 2][0]), "=r"(b[nq * 2][1]),
                          "=r"(b[nq * 2 + 1][0]), "=r"(b[nq * 2 + 1][1])
                        : "r"(addr) : "memory");
                }
#pragma unroll
                for (int mt = 0; mt < 2; mt++) {
#pragma unroll
                    for (int nt = 0; nt < 8; nt++) {
                        asm("mma.sync.aligned.m16n8k16.row.col.f32.f16.f16.f32 "
                            "{%0,%1,%2,%3}, {%4,%5,%6,%7}, {%8,%9}, {%0,%1,%2,%3};"
                            : "+f"(acc[mt][nt][0]), "+f"(acc[mt][nt][1]),
                              "+f"(acc[mt][nt][2]), "+f"(acc[mt][nt][3])
                            : "r"(a[mt][0]), "r"(a[mt][1]), "r"(a[mt][2]), "r"(a[mt][3]),
                              "r"(b[nt][0]), "r"(b[nt][1]));
                    }
                }
            }

            slot = (slot == STAGES - 1) ? 0 : slot + 1;
            nslot = (nslot == STAGES - 1) ? 0 : nslot + 1;
        }

        // epilogue with bias (regs -> C only; next tile's loads already in flight)
        {
            const int bm = (t >> 5) * BM;
            const int bn = (t & 31) * BN;
#pragma unroll
            for (int mt = 0; mt < 2; mt++) {
                int row0 = bm + wm * 32 + mt * 16 + (lane >> 2);
#pragma unroll
                for (int nt = 0; nt < 8; nt++) {
                    int col = bn + wn * 64 + nt * 8 + (lane & 3) * 2;
                    float b0 = __ldg(&bias[col]);
                    float b1 = __ldg(&bias[col + 1]);
                    float2 v0 = make_float2(acc[mt][nt][0] + b0, acc[mt][nt][1] + b1);
                    float2 v1 = make_float2(acc[mt][nt][2] + b0, acc[mt][nt][3] + b1);
                    *(float2*)&C[(size_t)row0 * NDIM + col] = v0;
                    *(float2*)&C[(size_t)(row0 + 8) * NDIM + col] = v1;
                }
            }
        }
        t += GRID_PERSIST;
    }
}

// ---------------------------------------------------------------------------
// Launch: inputs: x, W_q_packed, scales, zeros, bias
// ---------------------------------------------------------------------------
extern "C" void kernel_launch(void* const* d_in, const int* in_sizes, int n_in,
                              void* d_out, int out_size) {
    const float* x      = (const float*)d_in[0];
    const int*   wq     = (const int*)d_in[1];
    const float* scales = (const float*)d_in[2];
    const float* zeros  = (const float*)d_in[3];
    const float* bias   = (const float*)d_in[4];
    float* out = (float*)d_out;

    {   // merged prep: 8192 dequant blocks + 16384 cvt blocks
        k_prep<<<24576, 256>>>(x, wq, scales, zeros);
    }
    {
        cudaFuncSetAttribute(k_gemm, cudaFuncAttributeMaxDynamicSharedMemorySize, SM_TOTAL);
        k_gemm<<<GRID_PERSIST, 256, SM_TOTAL>>>(bias, out);
    }
}

// round 17
// speedup vs baseline: 1.3226x; 1.0243x over previous
#include <cuda_runtime.h>
#include <cuda_fp16.h>
#include <cstdint>

#define MDIM 4096
#define NDIM 4096
#define KDIM 4096

#define BM 128
#define BN 64
#define BK 64
#define KT_ITERS (KDIM / BK)      // 64

#define A_TILE_B 16384            // 128 rows x 128B (swizzled)
#define B_TILE_B 8192             // 64 rows x 128B (swizzled)
#define STAGE_B  (A_TILE_B + B_TILE_B)       // 24576
#define SM_TOTAL (2 * STAGE_B)               // 49152 (2 stages)

// Scratch (allocation-free rule: __device__ globals)
__device__ __half g_x16[(size_t)MDIM * KDIM];   // A [M][K]
__device__ __half g_w16[(size_t)KDIM * NDIM];   // W [K][N]

__device__ __forceinline__ uint32_t smem_u32(const void* p) {
    return (uint32_t)__cvta_generic_to_shared(p);
}

// ---------------------------------------------------------------------------
// Kernel 1: merged prep. Blocks [0, 8192): dequant W. [8192, 24576): cvt x.
// ---------------------------------------------------------------------------
__global__ void k_prep(const float* __restrict__ x,
                       const int* __restrict__ packed,
                       const float* __restrict__ scales,
                       const float* __restrict__ zeros) {
    int b = blockIdx.x;
    if (b < 8192) {
        // dequant: packed[i, n] holds k = i*8 + j in nibble j; group g = i/16
        int idx = b * 256 + threadIdx.x;       // over (K/8)*N = 2M
        int n = idx & (NDIM - 1);
        int i = idx >> 12;
        int g = i >> 4;
        float s = __ldg(&scales[g * NDIM + n]);
        float z = __ldg(&zeros[g * NDIM + n]);
        int p = __ldg(&packed[idx]);
#pragma unroll
        for (int j = 0; j < 8; j++) {
            int w = (p >> (4 * j)) & 15;
            g_w16[(size_t)(i * 8 + j) * NDIM + n] = __float2half(((float)w - z) * s);
        }
    } else {
        // x fp32 -> fp16, 4 elems/thread
        int idx = (b - 8192) * 256 + threadIdx.x;   // over 16M/4
        float4 v = ((const float4*)x)[idx];
        ((__half2*)g_x16)[idx * 2 + 0] = __floats2half2_rn(v.x, v.y);
        ((__half2*)g_x16)[idx * 2 + 1] = __floats2half2_rn(v.z, v.w);
    }
}

// ---------------------------------------------------------------------------
// Kernel 2: fp16 GEMM (mma.sync f32-acc), + bias.
// CTA tile 128x64, 128 threads (4 warps along M, warp tile 32x64),
// double-buffered cp.async (2 stages), XOR-swizzled 128B-row smem,
// 4 CTAs/SM -> 4 small independent barrier domains per SM (latency filling).
// Grid: x = N-tile (64), y = M-tile (32); adjacent bids share A rows in L2.
// ---------------------------------------------------------------------------
#define LOAD_STAGE(KT_, SLOT_) do {                                           \
    int k0_ = (KT_) * BK;                                                     \
    uint32_t sA_ = sbase + (SLOT_) * STAGE_B;                                 \
    uint32_t sB_ = sA_ + A_TILE_B;                                            \
    _Pragma("unroll")                                                         \
    for (int j_ = 0; j_ < 8; j_++) {                                          \
        int c_ = tid + j_ * 128;                                              \
        int ar_ = c_ >> 3, ac_ = c_ & 7;                                      \
        const __half* gA_ = g_x16 + (size_t)(bm + ar_) * KDIM + k0_ + ac_ * 8;\
        uint32_t soA_ = sA_ + ar_ * 128 + (((ac_ ^ (ar_ & 7))) << 4);         \
        asm volatile("cp.async.cg.shared.global [%0], [%1], 16;"              \
                     :: "r"(soA_), "l"(gA_) : "memory");                      \
    }                                                                         \
    _Pragma("unroll")                                                         \
    for (int j_ = 0; j_ < 4; j_++) {                                          \
        int c_ = tid + j_ * 128;                                              \
        int br_ = c_ >> 3, bc_ = c_ & 7;                                      \
        const __half* gB_ = g_w16 + (size_t)(k0_ + br_) * NDIM + bn + bc_ * 8;\
        uint32_t soB_ = sB_ + br_ * 128 + ((bc_ ^ (br_ & 7)) << 4);           \
        asm volatile("cp.async.cg.shared.global [%0], [%1], 16;"              \
                     :: "r"(soB_), "l"(gB_) : "memory");                      \
    }                                                                         \
    asm volatile("cp.async.commit_group;" ::: "memory");                      \
} while (0)

__global__ void __launch_bounds__(128, 4)
k_gemm(const float* __restrict__ bias, float* __restrict__ C) {
    extern __shared__ char smem[];
    const uint32_t sbase = smem_u32(smem);

    const int tid  = threadIdx.x;
    const int warp = tid >> 5;   // 4 warps along M
    const int lane = tid & 31;
    const int bm = blockIdx.y * BM;
    const int bn = blockIdx.x * BN;

    float acc[2][8][4];
#pragma unroll
    for (int mt = 0; mt < 2; mt++)
#pragma unroll
        for (int nt = 0; nt < 8; nt++)
#pragma unroll
            for (int r = 0; r < 4; r++) acc[mt][nt][r] = 0.0f;

    LOAD_STAGE(0, 0);
    LOAD_STAGE(1, 1);

    for (int kt = 0; kt < KT_ITERS; kt++) {
        if (kt < KT_ITERS - 1)
            asm volatile("cp.async.wait_group 1;" ::: "memory");
        else
            asm volatile("cp.async.wait_group 0;" ::: "memory");
        __syncthreads();

        const int slot = kt & 1;
        uint32_t sA = sbase + slot * STAGE_B;
        uint32_t sB = sA + A_TILE_B;

#pragma unroll
        for (int ks = 0; ks < 4; ks++) {          // 4 x k16 per BK=64
            uint32_t a[2][4];
#pragma unroll
            for (int mt = 0; mt < 2; mt++) {
                int row = warp * 32 + mt * 16 + (lane & 15);
                int c16 = ks * 2 + (lane >> 4);
                uint32_t addr = sA + row * 128 + ((c16 ^ (row & 7)) << 4);
                asm("ldmatrix.sync.aligned.m8n8.x4.shared.b16 {%0,%1,%2,%3}, [%4];"
                    : "=r"(a[mt][0]), "=r"(a[mt][1]), "=r"(a[mt][2]), "=r"(a[mt][3])
                    : "r"(addr) : "memory");
            }
            uint32_t b[8][2];
#pragma unroll
            for (int nq = 0; nq < 4; nq++) {
                int row = ks * 16 + (lane & 15);
                int c16 = nq * 2 + (lane >> 4);
                uint32_t addr = sB + row * 128 + ((c16 ^ (row & 7)) << 4);
                asm("ldmatrix.sync.aligned.m8n8.x4.trans.shared.b16 {%0,%1,%2,%3}, [%4];"
                    : "=r"(b[nq * 2][0]), "=r"(b[nq * 2][1]),
                      "=r"(b[nq * 2 + 1][0]), "=r"(b[nq * 2 + 1][1])
                    : "r"(addr) : "memory");
            }
#pragma unroll
            for (int mt = 0; mt < 2; mt++) {
#pragma unroll
                for (int nt = 0; nt < 8; nt++) {
                    asm("mma.sync.aligned.m16n8k16.row.col.f32.f16.f16.f32 "
                        "{%0,%1,%2,%3}, {%4,%5,%6,%7}, {%8,%9}, {%0,%1,%2,%3};"
                        : "+f"(acc[mt][nt][0]), "+f"(acc[mt][nt][1]),
                          "+f"(acc[mt][nt][2]), "+f"(acc[mt][nt][3])
                        : "r"(a[mt][0]), "r"(a[mt][1]), "r"(a[mt][2]), "r"(a[mt][3]),
                          "r"(b[nt][0]), "r"(b[nt][1]));
                }
            }
        }

        // WAR guard before overwriting the buffer just consumed
        if (kt + 2 < KT_ITERS) {
            __syncthreads();
            LOAD_STAGE(kt + 2, slot);
        }
    }

    // epilogue with bias
#pragma unroll
    for (int mt = 0; mt < 2; mt++) {
        int row0 = bm + warp * 32 + mt * 16 + (lane >> 2);
#pragma unroll
        for (int nt = 0; nt < 8; nt++) {
            int col = bn + nt * 8 + (lane & 3) * 2;
            float b0 = __ldg(&bias[col]);
            float b1 = __ldg(&bias[col + 1]);
            float2 v0 = make_float2(acc[mt][nt][0] + b0, acc[mt][nt][1] + b1);
            float2 v1 = make_float2(acc[mt][nt][2] + b0, acc[mt][nt][3] + b1);
            *(float2*)&C[(size_t)row0 * NDIM + col] = v0;
            *(float2*)&C[(size_t)(row0 + 8) * NDIM + col] = v1;
        }
    }
}

// ---------------------------------------------------------------------------
// Launch: inputs: x, W_q_packed, scales, zeros, bias
// ---------------------------------------------------------------------------
extern "C" void kernel_launch(void* const* d_in, const int* in_sizes, int n_in,
                              void* d_out, int out_size) {
    const float* x      = (const float*)d_in[0];
    const int*   wq     = (const int*)d_in[1];
    const float* scales = (const float*)d_in[2];
    const float* zeros  = (const float*)d_in[3];
    const float* bias   = (const float*)d_in[4];
    float* out = (float*)d_out;

    {   // merged prep: 8192 dequant blocks + 16384 cvt blocks
        k_prep<<<24576, 256>>>(x, wq, scales, zeros);
    }
    {
        cudaFuncSetAttribute(k_gemm, cudaFuncAttributeMaxDynamicSharedMemorySize, SM_TOTAL);
        dim3 grid(NDIM / BN, MDIM / BM);     // (64, 32)
        k_gemm<<<grid, 128, SM_TOTAL>>>(bias, out);
    }
}